// round 1
// baseline (speedup 1.0000x reference)
#include <cuda_runtime.h>
#include <cstdint>
#include <cstddef>

#define B_   128
#define C_   2048
#define HW_  196
#define ND_  32
#define NA_  1845

// Scratch for attended features (cudaMalloc is forbidden) — 1 MB.
__device__ float g_att[B_ * C_];

// ---------------------------------------------------------------------------
// Kernel 1: attended[b][c] = (1/196) * sum_hw mask[b][hw] * features[b][c][hw]
// One warp per (b,c) row. 196 floats = 49 float4 (row stride 784 B, 16-aligned).
// ---------------------------------------------------------------------------
__global__ void __launch_bounds__(256) k_attend(const float* __restrict__ mask,
                                                const float* __restrict__ feat)
{
    int gw   = (blockIdx.x * 256 + threadIdx.x) >> 5;   // global warp = row index
    int lane = threadIdx.x & 31;
    if (gw >= B_ * C_) return;
    int b = gw >> 11;                                    // 2048 rows per sample

    const float4* f  = (const float4*)(feat + (size_t)gw * HW_);
    const float4* mk = (const float4*)(mask + (size_t)b  * HW_);

    float4 a0 = f[lane], m0 = mk[lane];
    float s = a0.x * m0.x + a0.y * m0.y + a0.z * m0.z + a0.w * m0.w;
    if (lane < 17) {                                     // float4 indices 32..48
        float4 a1 = f[lane + 32], m1 = mk[lane + 32];
        s += a1.x * m1.x + a1.y * m1.y + a1.z * m1.z + a1.w * m1.w;
    }
    #pragma unroll
    for (int o = 16; o; o >>= 1) s += __shfl_xor_sync(0xffffffffu, s, o);
    if (lane == 0) g_att[gw] = s * (1.0f / 196.0f);
}

// ---------------------------------------------------------------------------
// Packed f32x2 FMA (2 MACs per issue slot; ptxas never auto-fuses this).
// ---------------------------------------------------------------------------
__device__ __forceinline__ void fma2(unsigned long long& d,
                                     unsigned long long a,
                                     unsigned long long b)
{
    asm("fma.rn.f32x2 %0, %1, %2, %0;" : "+l"(d) : "l"(a), "l"(b));
}

// ---------------------------------------------------------------------------
// One GEMM pass: 4 answer rows x MB samples, W streamed once.
// acc[r][j] is an f32x2 pair; each 16B chunk contributes 2 packed FMAs.
// ---------------------------------------------------------------------------
template <int MB>
__device__ __forceinline__ void gemm_pass(int d, int a0, int lane,
                                          const int* bj,
                                          const float* __restrict__ W,
                                          const float* __restrict__ bias,
                                          float* __restrict__ out)
{
    const ulonglong2* Wp[4];
    #pragma unroll
    for (int r = 0; r < 4; r++) {
        int ar = a0 + r;
        if (ar > NA_ - 1) ar = NA_ - 1;                  // clamp; skip writeback later
        Wp[r] = (const ulonglong2*)(W + ((size_t)d * NA_ + ar) * C_);
    }
    const ulonglong2* Ap[MB];
    #pragma unroll
    for (int j = 0; j < MB; j++)
        Ap[j] = (const ulonglong2*)(g_att + (size_t)bj[j] * C_);

    unsigned long long acc[4][MB];
    #pragma unroll
    for (int r = 0; r < 4; r++)
        #pragma unroll
        for (int j = 0; j < MB; j++) acc[r][j] = 0ull;

    // 2048 floats = 512 x 16B chunks; lane-strided, coalesced 512B per warp-load.
    for (int c = lane; c < C_ / 4; c += 32) {
        ulonglong2 w[4];
        #pragma unroll
        for (int r = 0; r < 4; r++) w[r] = Wp[r][c];
        #pragma unroll
        for (int j = 0; j < MB; j++) {
            ulonglong2 x = Ap[j][c];
            #pragma unroll
            for (int r = 0; r < 4; r++) {
                fma2(acc[r][j], w[r].x, x.x);
                fma2(acc[r][j], w[r].y, x.y);
            }
        }
    }

    #pragma unroll
    for (int r = 0; r < 4; r++) {
        int a = a0 + r;
        #pragma unroll
        for (int j = 0; j < MB; j++) {
            float v = __uint_as_float((unsigned)(acc[r][j] & 0xffffffffu))
                    + __uint_as_float((unsigned)(acc[r][j] >> 32));
            #pragma unroll
            for (int o = 16; o; o >>= 1) v += __shfl_xor_sync(0xffffffffu, v, o);
            if (lane == 0 && a < NA_)
                out[(size_t)bj[j] * NA_ + a] = v + bias[(size_t)d * NA_ + a];
        }
    }
}

// ---------------------------------------------------------------------------
// Kernel 2: grouped GEMM. Grid (ceil(1845/32)=58, 32 descriptors).
// Block builds its descriptor's sample list, each warp does 4 answers.
// ---------------------------------------------------------------------------
__global__ void __launch_bounds__(256) k_gemm(const void* __restrict__ inst_raw,
                                              const float* __restrict__ W,
                                              const float* __restrict__ bias,
                                              float* __restrict__ out)
{
    __shared__ int s_list[B_];
    __shared__ int s_cnt;
    __shared__ int s_is64;

    if (threadIdx.x == 0) {
        // Detect int64 vs int32 layout: first 512 B is in-bounds either way.
        // int64 (values 0..31) => every odd 32-bit word is zero.
        const unsigned* pw = (const unsigned*)inst_raw;
        unsigned orv = 0;
        for (int i = 1; i < 128; i += 2) orv |= pw[i];
        s_is64 = (orv == 0) ? 1 : 0;
        s_cnt  = 0;
    }
    __syncthreads();

    int d = blockIdx.y;
    if (threadIdx.x < B_) {
        int v = s_is64 ? (int)((const long long*)inst_raw)[threadIdx.x]
                       : ((const int*)inst_raw)[threadIdx.x];
        if (v == d) {
            int p = atomicAdd(&s_cnt, 1);
            s_list[p] = threadIdx.x;
        }
    }
    __syncthreads();

    int m = s_cnt;
    if (m == 0) return;                                  // unused descriptor: no W read

    int warp = threadIdx.x >> 5;
    int lane = threadIdx.x & 31;
    int a0 = (blockIdx.x * 8 + warp) * 4;
    if (a0 >= NA_) return;

    for (int base = 0; base < m; base += 8) {
        int mb = m - base; if (mb > 8) mb = 8;
        int bj[8];
        #pragma unroll
        for (int j = 0; j < 8; j++) bj[j] = s_list[base + ((j < mb) ? j : 0)];
        switch (mb) {                                     // fully-unrolled, zero-waste
            case 1: gemm_pass<1>(d, a0, lane, bj, W, bias, out); break;
            case 2: gemm_pass<2>(d, a0, lane, bj, W, bias, out); break;
            case 3: gemm_pass<3>(d, a0, lane, bj, W, bias, out); break;
            case 4: gemm_pass<4>(d, a0, lane, bj, W, bias, out); break;
            case 5: gemm_pass<5>(d, a0, lane, bj, W, bias, out); break;
            case 6: gemm_pass<6>(d, a0, lane, bj, W, bias, out); break;
            case 7: gemm_pass<7>(d, a0, lane, bj, W, bias, out); break;
            default: gemm_pass<8>(d, a0, lane, bj, W, bias, out); break;
        }
    }
}

// ---------------------------------------------------------------------------
// Inputs (metadata order): mask f32[128,1,14,14], features f32[128,2048,14,14],
// instance int[128], W f32[32,1845,2048], b f32[32,1845]. Output f32[128,1845].
// ---------------------------------------------------------------------------
extern "C" void kernel_launch(void* const* d_in, const int* in_sizes, int n_in,
                              void* d_out, int out_size)
{
    const float* mask = (const float*)d_in[0];
    const float* feat = (const float*)d_in[1];
    const void*  inst = d_in[2];
    const float* W    = (const float*)d_in[3];
    const float* bias = (const float*)d_in[4];
    float* out = (float*)d_out;

    int blocks1 = (B_ * C_) / 8;            // 32768 blocks, warp per (b,c) row
    k_attend<<<blocks1, 256>>>(mask, feat);

    dim3 g2((NA_ + 31) / 32, ND_);          // (58, 32)
    k_gemm<<<g2, 256>>>(inst, W, bias, out);
}

// round 2
// speedup vs baseline: 1.3197x; 1.3197x over previous
#include <cuda_runtime.h>
#include <cstdint>
#include <cstddef>

#define B_   128
#define C_   2048
#define HW_  196
#define ND_  32
#define NA_  1845

// Scratch for attended features (cudaMalloc is forbidden) — 1 MB.
__device__ float g_att[B_ * C_];

// ---------------------------------------------------------------------------
// Kernel 1: attended[b][c] = (1/196) * sum_hw mask[b][hw] * features[b][c][hw]
// One warp per (b,c) row. 196 floats = 49 float4 (row stride 784 B, 16-aligned).
// Measured ~33us at ~6.2 TB/s — near HBM roofline, leave as-is.
// ---------------------------------------------------------------------------
__global__ void __launch_bounds__(256) k_attend(const float* __restrict__ mask,
                                                const float* __restrict__ feat)
{
    int gw   = (blockIdx.x * 256 + threadIdx.x) >> 5;   // global warp = row index
    int lane = threadIdx.x & 31;
    if (gw >= B_ * C_) return;
    int b = gw >> 11;                                    // 2048 rows per sample

    const float4* f  = (const float4*)(feat + (size_t)gw * HW_);
    const float4* mk = (const float4*)(mask + (size_t)b  * HW_);

    float4 a0 = f[lane], m0 = mk[lane];
    float s = a0.x * m0.x + a0.y * m0.y + a0.z * m0.z + a0.w * m0.w;
    if (lane < 17) {                                     // float4 indices 32..48
        float4 a1 = f[lane + 32], m1 = mk[lane + 32];
        s += a1.x * m1.x + a1.y * m1.y + a1.z * m1.z + a1.w * m1.w;
    }
    #pragma unroll
    for (int o = 16; o; o >>= 1) s += __shfl_xor_sync(0xffffffffu, s, o);
    if (lane == 0) g_att[gw] = s * (1.0f / 196.0f);
}

// ---------------------------------------------------------------------------
// Packed f32x2 FMA (2 MACs per issue slot; ptxas never auto-fuses this).
// ---------------------------------------------------------------------------
__device__ __forceinline__ void fma2(unsigned long long& d,
                                     unsigned long long a,
                                     unsigned long long b)
{
    asm("fma.rn.f32x2 %0, %1, %2, %0;" : "+l"(d) : "l"(a), "l"(b));
}

// ---------------------------------------------------------------------------
// One GEMM pass: 4 answer rows x MB (<=4) samples, W streamed once.
// acc[r][j] is an f32x2 pair; each 16B chunk contributes 2 packed FMAs.
// W rows are consecutive answers: index with c + r*512 off one base pointer
// (saves 3 pointer pairs of registers).
// ---------------------------------------------------------------------------
template <int MB>
__device__ __forceinline__ void gemm_pass(int d, int a0, int lane,
                                          const int* bj,
                                          const float* __restrict__ W,
                                          const float* __restrict__ bias,
                                          float* __restrict__ out)
{
    // Clamp the row block so all 4 rows stay in-bounds (writeback re-checks).
    int a0c = a0;
    if (a0c > NA_ - 4) a0c = NA_ - 4;
    const ulonglong2* Wp = (const ulonglong2*)(W + ((size_t)d * NA_ + a0c) * C_);

    const ulonglong2* Ap[MB];
    #pragma unroll
    for (int j = 0; j < MB; j++)
        Ap[j] = (const ulonglong2*)(g_att + (size_t)bj[j] * C_);

    unsigned long long acc[4][MB];
    #pragma unroll
    for (int r = 0; r < 4; r++)
        #pragma unroll
        for (int j = 0; j < MB; j++) acc[r][j] = 0ull;

    // 2048 floats = 512 x 16B chunks; lane-strided, coalesced 512B per warp-load.
    // 512 chunks per W row -> row r at offset r*512.
    for (int c = lane; c < C_ / 4; c += 32) {
        ulonglong2 w[4];
        #pragma unroll
        for (int r = 0; r < 4; r++) w[r] = Wp[c + r * 512];
        ulonglong2 x[MB];
        #pragma unroll
        for (int j = 0; j < MB; j++) x[j] = Ap[j][c];
        #pragma unroll
        for (int j = 0; j < MB; j++) {
            #pragma unroll
            for (int r = 0; r < 4; r++) {
                fma2(acc[r][j], w[r].x, x[j].x);
                fma2(acc[r][j], w[r].y, x[j].y);
            }
        }
    }

    #pragma unroll
    for (int r = 0; r < 4; r++) {
        int a = a0c + r;
        #pragma unroll
        for (int j = 0; j < MB; j++) {
            float v = __uint_as_float((unsigned)(acc[r][j] & 0xffffffffu))
                    + __uint_as_float((unsigned)(acc[r][j] >> 32));
            #pragma unroll
            for (int o = 16; o; o >>= 1) v += __shfl_xor_sync(0xffffffffu, v, o);
            if (lane == 0 && a >= a0)                    // skip clamp-duplicated rows
                out[(size_t)bj[j] * NA_ + a] = v + bias[(size_t)d * NA_ + a];
        }
    }
}

// ---------------------------------------------------------------------------
// Kernel 2: grouped GEMM. Grid (ceil(1845/32)=58, 32 descriptors).
// Block builds its descriptor's sample list, each warp does 4 answers.
// MB capped at 4: passes beyond the first re-read the block's 256KB W slice
// from L2, keeping DRAM traffic at the 483MB floor while acc regs stay small.
// ---------------------------------------------------------------------------
__global__ void __launch_bounds__(256, 3) k_gemm(const void* __restrict__ inst_raw,
                                                 const float* __restrict__ W,
                                                 const float* __restrict__ bias,
                                                 float* __restrict__ out)
{
    __shared__ int s_list[B_];
    __shared__ int s_cnt;
    __shared__ int s_is64;

    if (threadIdx.x == 0) {
        // Detect int64 vs int32 layout: first 512 B is in-bounds either way.
        // int64 (values 0..31) => every odd 32-bit word is zero.
        const unsigned* pw = (const unsigned*)inst_raw;
        unsigned orv = 0;
        for (int i = 1; i < 128; i += 2) orv |= pw[i];
        s_is64 = (orv == 0) ? 1 : 0;
        s_cnt  = 0;
    }
    __syncthreads();

    int d = blockIdx.y;
    if (threadIdx.x < B_) {
        int v = s_is64 ? (int)((const long long*)inst_raw)[threadIdx.x]
                       : ((const int*)inst_raw)[threadIdx.x];
        if (v == d) {
            int p = atomicAdd(&s_cnt, 1);
            s_list[p] = threadIdx.x;
        }
    }
    __syncthreads();

    int m = s_cnt;
    if (m == 0) return;                                  // unused descriptor: no W read

    int warp = threadIdx.x >> 5;
    int lane = threadIdx.x & 31;
    int a0 = (blockIdx.x * 8 + warp) * 4;
    if (a0 >= NA_) return;

    for (int base = 0; base < m; base += 4) {
        int mb = m - base; if (mb > 4) mb = 4;
        int bj[4];
        #pragma unroll
        for (int j = 0; j < 4; j++) bj[j] = s_list[base + ((j < mb) ? j : 0)];
        switch (mb) {                                     // fully-unrolled, zero-waste
            case 1:  gemm_pass<1>(d, a0, lane, bj, W, bias, out); break;
            case 2:  gemm_pass<2>(d, a0, lane, bj, W, bias, out); break;
            case 3:  gemm_pass<3>(d, a0, lane, bj, W, bias, out); break;
            default: gemm_pass<4>(d, a0, lane, bj, W, bias, out); break;
        }
    }
}

// ---------------------------------------------------------------------------
// Inputs (metadata order): mask f32[128,1,14,14], features f32[128,2048,14,14],
// instance int[128], W f32[32,1845,2048], b f32[32,1845]. Output f32[128,1845].
// ---------------------------------------------------------------------------
extern "C" void kernel_launch(void* const* d_in, const int* in_sizes, int n_in,
                              void* d_out, int out_size)
{
    const float* mask = (const float*)d_in[0];
    const float* feat = (const float*)d_in[1];
    const void*  inst = d_in[2];
    const float* W    = (const float*)d_in[3];
    const float* bias = (const float*)d_in[4];
    float* out = (float*)d_out;

    int blocks1 = (B_ * C_) / 8;            // 32768 blocks, warp per (b,c) row
    k_attend<<<blocks1, 256>>>(mask, feat);

    dim3 g2((NA_ + 31) / 32, ND_);          // (58, 32)
    k_gemm<<<g2, 256>>>(inst, W, bias, out);
}

// round 4
// speedup vs baseline: 1.5321x; 1.1609x over previous
#include <cuda_runtime.h>
#include <cstdint>
#include <cstddef>

#define B_   128
#define C_   2048
#define HW_  196
#define ND_  32
#define NA_  1845

#define CK     256          // floats per k-chunk (1KB per W row)
#define NCHUNK 8            // 2048 / 256
#define NBUF   3            // triple buffer -> 1 barrier per chunk
#define ATILE  32           // answer rows per block

// Scratch for attended features (cudaMalloc is forbidden) — 1 MB.
__device__ float g_att[B_ * C_];

// ---- dynamic smem layout (bytes) ----
#define SM_WSZ  (NBUF * ATILE * CK * 4)   // 98304
#define SM_XSZ  (NBUF * 4 * CK * 4)       // 12288
#define SM_W    0
#define SM_X    (SM_W + SM_WSZ)
#define SM_LIST (SM_X + SM_XSZ)           // int[128]
#define SM_BJ   (SM_LIST + 128 * 4)       // int[4]
#define SM_CNT  (SM_BJ + 16)
#define SM_IS64 (SM_CNT + 4)
#define SM_TOT  (SM_IS64 + 4)             // ~111.1 KB -> 2 blocks/SM

// ---------------------------------------------------------------------------
// Kernel 1: attended[b][c] = (1/196) * sum_hw mask[b][hw] * features[b][c][hw]
// One warp per (b,c) row; measured near HBM roofline — unchanged.
// ---------------------------------------------------------------------------
__global__ void __launch_bounds__(256) k_attend(const float* __restrict__ mask,
                                                const float* __restrict__ feat)
{
    int gw   = (blockIdx.x * 256 + threadIdx.x) >> 5;
    int lane = threadIdx.x & 31;
    if (gw >= B_ * C_) return;
    int b = gw >> 11;

    const float4* f  = (const float4*)(feat + (size_t)gw * HW_);
    const float4* mk = (const float4*)(mask + (size_t)b  * HW_);

    float4 a0 = f[lane], m0 = mk[lane];
    float s = a0.x * m0.x + a0.y * m0.y + a0.z * m0.z + a0.w * m0.w;
    if (lane < 17) {
        float4 a1 = f[lane + 32], m1 = mk[lane + 32];
        s += a1.x * m1.x + a1.y * m1.y + a1.z * m1.z + a1.w * m1.w;
    }
    #pragma unroll
    for (int o = 16; o; o >>= 1) s += __shfl_xor_sync(0xffffffffu, s, o);
    if (lane == 0) g_att[gw] = s * (1.0f / 196.0f);
}

// ---------------------------------------------------------------------------
// Helpers
// ---------------------------------------------------------------------------
__device__ __forceinline__ void fma2(unsigned long long& d,
                                     unsigned long long a,
                                     unsigned long long b)
{
    asm("fma.rn.f32x2 %0, %1, %2, %0;" : "+l"(d) : "l"(a), "l"(b));
}

__device__ __forceinline__ uint32_t smem_u32(const void* p) {
    uint32_t a;
    asm("{ .reg .u64 t; cvta.to.shared.u64 t, %1; cvt.u32.u64 %0, t; }"
        : "=r"(a) : "l"(p));
    return a;
}

__device__ __forceinline__ void cp16(uint32_t saddr, const void* gaddr) {
    asm volatile("cp.async.cg.shared.global [%0], [%1], 16;"
                 :: "r"(saddr), "l"(gaddr));
}
__device__ __forceinline__ void cp_commit() {
    asm volatile("cp.async.commit_group;");
}
template <int N>
__device__ __forceinline__ void cp_wait() {
    asm volatile("cp.async.wait_group %0;" :: "n"(N));
}

// ---------------------------------------------------------------------------
// Issue one k-chunk stage: W[32 rows][CK] + X[4 samples][CK] -> smem buf.
// 256 threads: W = 2048 x 16B chunks (8 per thread), X = 256 x 16B (1 each).
// ---------------------------------------------------------------------------
__device__ __forceinline__ void issue_stage(uint32_t smb,
                                            const float* __restrict__ W,
                                            size_t wrow0, int k0, int buf,
                                            int tid, int bjx)
{
    uint32_t wdst = smb + SM_W + buf * (ATILE * CK * 4) + tid * 16;
    const float* gw = W + wrow0 + (size_t)(tid >> 6) * C_ + k0 + (tid & 63) * 4;
    #pragma unroll
    for (int t = 0; t < 8; t++)                 // row = t*4 + (tid>>6)
        cp16(wdst + t * 4096, gw + (size_t)(t * 4) * C_);

    uint32_t xdst = smb + SM_X + buf * (4 * CK * 4) + tid * 16;
    cp16(xdst, g_att + (size_t)bjx * C_ + k0 + (tid & 63) * 4);
    cp_commit();
}

// ---------------------------------------------------------------------------
// One full pass over C for one (<=4)-sample group: 3-buffer cp.async pipeline.
// bj[] lives in REGISTERS (compile-time-indexed) — the writeback below runs
// after the last internal barrier, so it must not touch shared state that the
// next pass rewrites (R3 bug).
// ---------------------------------------------------------------------------
template <int MB>
__device__ __forceinline__ void run_pass(uint32_t smb, char* sm,
                                         const float* __restrict__ W,
                                         size_t wrow0, int tid, int lane,
                                         int w4, int bjx, const int* bj,
                                         int a0c, int a0nom, int d,
                                         const float* __restrict__ bias,
                                         float* __restrict__ out)
{
    unsigned long long acc[4][MB];
    #pragma unroll
    for (int r = 0; r < 4; r++)
        #pragma unroll
        for (int j = 0; j < MB; j++) acc[r][j] = 0ull;

    issue_stage(smb, W, wrow0, 0, 0, tid, bjx);

    for (int k = 0; k < NCHUNK; k++) {
        int buf = k % NBUF;
        if (k + 1 < NCHUNK) {
            issue_stage(smb, W, wrow0, (k + 1) * CK, (k + 1) % NBUF, tid, bjx);
            cp_wait<1>();
        } else {
            cp_wait<0>();
        }
        __syncthreads();                         // stage k visible to all

        const float* Wb = (const float*)(sm + SM_W + buf * (ATILE * CK * 4));
        const float* Xb = (const float*)(sm + SM_X + buf * (4 * CK * 4));
        #pragma unroll
        for (int s = 0; s < 2; s++) {            // CK/4 = 64 float4, 2 lane-steps
            int c = lane + s * 32;
            ulonglong2 w[4];
            #pragma unroll
            for (int r = 0; r < 4; r++)
                w[r] = ((const ulonglong2*)(Wb + (w4 + r) * CK))[c];
            #pragma unroll
            for (int j = 0; j < MB; j++) {
                ulonglong2 x = ((const ulonglong2*)(Xb + j * CK))[c];
                #pragma unroll
                for (int r = 0; r < 4; r++) {
                    fma2(acc[r][j], w[r].x, x.x);
                    fma2(acc[r][j], w[r].y, x.y);
                }
            }
        }
        // No trailing barrier: with 3 buffers, iter k+1's issue overwrites the
        // buffer last read at stage k-1, protected by this iter's barrier.
    }

    #pragma unroll
    for (int r = 0; r < 4; r++) {
        int a = a0c + w4 + r;
        #pragma unroll
        for (int j = 0; j < MB; j++) {
            float v = __uint_as_float((unsigned)(acc[r][j] & 0xffffffffu))
                    + __uint_as_float((unsigned)(acc[r][j] >> 32));
            #pragma unroll
            for (int o = 16; o; o >>= 1) v += __shfl_xor_sync(0xffffffffu, v, o);
            if (lane == 0 && a >= a0nom)         // skip clamp-duplicated rows
                out[(size_t)bj[j] * NA_ + a] = v + bias[(size_t)d * NA_ + a];
        }
    }
}

// ---------------------------------------------------------------------------
// Kernel 2: grouped GEMM, cp.async-staged. Grid (58, 32), 256 threads.
// ---------------------------------------------------------------------------
__global__ void __launch_bounds__(256, 2) k_gemm(const void* __restrict__ inst_raw,
                                                 const float* __restrict__ W,
                                                 const float* __restrict__ bias,
                                                 float* __restrict__ out)
{
    extern __shared__ char sm[];
    uint32_t smb = smem_u32(sm);
    int* s_list = (int*)(sm + SM_LIST);
    int* s_bj   = (int*)(sm + SM_BJ);
    int* s_cnt  = (int*)(sm + SM_CNT);
    int* s_is64 = (int*)(sm + SM_IS64);

    if (threadIdx.x == 0) {
        // Detect int64 vs int32 instance layout (values 0..31 => odd words 0).
        const unsigned* pw = (const unsigned*)inst_raw;
        unsigned orv = 0;
        for (int i = 1; i < 128; i += 2) orv |= pw[i];
        *s_is64 = (orv == 0) ? 1 : 0;
        *s_cnt  = 0;
    }
    __syncthreads();

    int d = blockIdx.y;
    if (threadIdx.x < B_) {
        int v = *s_is64 ? (int)((const long long*)inst_raw)[threadIdx.x]
                        : ((const int*)inst_raw)[threadIdx.x];
        if (v == d) {
            int p = atomicAdd(s_cnt, 1);
            s_list[p] = threadIdx.x;
        }
    }
    __syncthreads();

    int m = *s_cnt;
    if (m == 0) return;                          // unused descriptor: no W read

    int tid  = threadIdx.x;
    int lane = tid & 31;
    int w4   = (tid >> 5) * 4;                   // warp's 4 rows within the tile
    int a0nom = blockIdx.x * ATILE;
    int a0c   = a0nom > NA_ - ATILE ? NA_ - ATILE : a0nom;
    size_t wrow0 = ((size_t)d * NA_ + a0c) * C_;

    for (int base = 0; base < m; base += 4) {
        int mb = m - base; if (mb > 4) mb = 4;
        if (tid < 4) s_bj[tid] = s_list[base + (tid < mb ? tid : mb - 1)];
        __syncthreads();                         // publishes s_bj; fences prior bufs

        // Snapshot into registers NOW (before any thread can reach the next
        // iteration's s_bj write). Writeback later reads only these.
        int bj[4];
        #pragma unroll
        for (int j = 0; j < 4; j++) bj[j] = s_bj[j];
        int bjx = bj[tid >> 6];                  // X row this thread stages

        switch (mb) {
            case 1:  run_pass<1>(smb, sm, W, wrow0, tid, lane, w4, bjx, bj,
                                 a0c, a0nom, d, bias, out); break;
            case 2:  run_pass<2>(smb, sm, W, wrow0, tid, lane, w4, bjx, bj,
                                 a0c, a0nom, d, bias, out); break;
            case 3:  run_pass<3>(smb, sm, W, wrow0, tid, lane, w4, bjx, bj,
                                 a0c, a0nom, d, bias, out); break;
            default: run_pass<4>(smb, sm, W, wrow0, tid, lane, w4, bjx, bj,
                                 a0c, a0nom, d, bias, out); break;
        }
    }
}

// ---------------------------------------------------------------------------
// Inputs (metadata order): mask f32[128,1,14,14], features f32[128,2048,14,14],
// instance int[128], W f32[32,1845,2048], b f32[32,1845]. Output f32[128,1845].
// ---------------------------------------------------------------------------
extern "C" void kernel_launch(void* const* d_in, const int* in_sizes, int n_in,
                              void* d_out, int out_size)
{
    const float* mask = (const float*)d_in[0];
    const float* feat = (const float*)d_in[1];
    const void*  inst = d_in[2];
    const float* W    = (const float*)d_in[3];
    const float* bias = (const float*)d_in[4];
    float* out = (float*)d_out;

    int blocks1 = (B_ * C_) / 8;                 // warp per (b,c) row
    k_attend<<<blocks1, 256>>>(mask, feat);

    cudaFuncSetAttribute(k_gemm, cudaFuncAttributeMaxDynamicSharedMemorySize,
                         SM_TOT);
    dim3 g2((NA_ + ATILE - 1) / ATILE, ND_);     // (58, 32)
    k_gemm<<<g2, 256, SM_TOT>>>(inst, W, bias, out);
}